// round 16
// baseline (speedup 1.0000x reference)
#include <cuda_runtime.h>
#include <cuda_fp16.h>
#include <math.h>
#include <stdint.h>

#define NN 100000
#define NE 1600000
#define DH 128
#define DO 64

// ---------------- device scratch (static; no allocation allowed) ----------------
__device__ int      g_deg[NN];      // zero-initialized at load; re-zeroed by final agg each call
__device__ int      g_fill[NN];     // zeroed by k_scan3 each call (before k_csr)
__device__ int      g_rowptr[NN];
__device__ int      g_csr[NE];
__device__ uint4    g_z4[(size_t)NN * DH * 2 / 16];   // fp16 Z backing
__device__ uint4    g_hh[(size_t)NN * DH * 2 / 16];   // fp16 H backing (also holds X16 before agg1)
__device__ int      g_bsums[128];
__device__ uint32_t g_wb[128 * 64];   // packed fp16x2 weights, natural k-pair order

// ---------------- helpers ----------------
__device__ __forceinline__ uint32_t packh2(float x, float y) {
    __half2 h = __floats2half2_rn(x, y);
    return *(uint32_t*)&h;
}
__device__ __forceinline__ uint32_t s2u(const void* p) {
    uint32_t a;
    asm("{ .reg .u64 t; cvta.to.shared.u64 t, %1; cvt.u32.u64 %0, t; }" : "=r"(a) : "l"(p));
    return a;
}
__device__ __forceinline__ void cp16(uint32_t dst, const void* src) {
    asm volatile("cp.async.cg.shared.global [%0], [%1], 16;" :: "r"(dst), "l"(src));
}

__device__ __forceinline__ void mma_f16(float* c, const uint32_t* a, uint32_t b0, uint32_t b1) {
    asm volatile(
        "mma.sync.aligned.m16n8k16.row.col.f32.f16.f16.f32 "
        "{%0,%1,%2,%3}, {%4,%5,%6,%7}, {%8,%9}, {%0,%1,%2,%3};"
        : "+f"(c[0]), "+f"(c[1]), "+f"(c[2]), "+f"(c[3])
        : "r"(a[0]), "r"(a[1]), "r"(a[2]), "r"(a[3]), "r"(b0), "r"(b1));
}

// ---------------- prep kernels ----------------
__global__ void k_hist(const int* __restrict__ dst) {
    int i = blockIdx.x * 256 + threadIdx.x;
    if (i < NE) atomicAdd(&g_deg[dst[i]], 1);
}
__global__ void k_scan1() {
    __shared__ int s[1024];
    int t = threadIdx.x;
    int i = blockIdx.x * 1024 + t;
    int val = (i < NN) ? g_deg[i] : 0;
    s[t] = val;
    __syncthreads();
    for (int off = 1; off < 1024; off <<= 1) {
        int x = (t >= off) ? s[t - off] : 0;
        __syncthreads();
        if (t >= off) s[t] += x;
        __syncthreads();
    }
    if (i < NN) g_rowptr[i] = s[t] - val;
    if (t == 1023) g_bsums[blockIdx.x] = s[1023];
}
// scan of block sums fused in (every block redundantly scans the 98 bsums),
// plus g_fill zeroing for k_csr.
__global__ void k_scan3(int nb) {
    __shared__ int s[128];
    __shared__ int excl;
    int t = threadIdx.x;
    int val = 0;
    if (t < 128) { val = (t < nb) ? g_bsums[t] : 0; s[t] = val; }
    __syncthreads();
    for (int off = 1; off < 128; off <<= 1) {
        int x = (t < 128 && t >= off) ? s[t - off] : 0;
        __syncthreads();
        if (t < 128 && t >= off) s[t] += x;
        __syncthreads();
    }
    if (t == (int)blockIdx.x) excl = s[t] - val;   // exclusive prefix of this block
    __syncthreads();
    int i = blockIdx.x * 1024 + t;
    if (i < NN) { g_rowptr[i] += excl; g_fill[i] = 0; }
}
__global__ void k_csr(const int* __restrict__ src, const int* __restrict__ dst) {
    int i = blockIdx.x * 256 + threadIdx.x;
    if (i < NE) {
        int d = dst[i];
        int pos = g_rowptr[d] + atomicAdd(&g_fill[d], 1);
        g_csr[pos] = src[i];
    }
}

// ---------------- conversions ----------------
// weights: fp32 -> fp16x2, natural k-pair order (k-perm: thread qp owns phys k 16ks+4qp..+3)
__global__ void k_wconv(const float* __restrict__ W, int outc) {
    int i = blockIdx.x * 256 + threadIdx.x;
    if (i >= outc * 64) return;
    int col = i >> 6, kp = i & 63;
    g_wb[col * 64 + kp] = packh2(W[(2 * kp) * outc + col], W[(2 * kp + 1) * outc + col]);
}
// X: fp32 -> fp16, streaming
__global__ void k_xconv(const float* __restrict__ X, __half* __restrict__ Xh) {
    int i = blockIdx.x * 256 + threadIdx.x;   // handles 4 floats
    if (i < NN * DH / 4) {
        float4 x = ((const float4*)X)[i];
        uint2 o;
        o.x = packh2(x.x, x.y);
        o.y = packh2(x.z, x.w);
        ((uint2*)Xh)[i] = o;
    }
}

// ---------------- mma.sync GEMM: Z[v][t] = dinv[v] * dot(X[v,:], W[:,t]) ----------------
// M-tile 128, block 256 (8 warps): warp wid owns rows wid*16..+15, FULL N.
// A (fp16) staged verbatim via cp.async into smem rows of stride 72 words (288B):
// coalesced 16B granules, no ALU, no scatter. Fragment loads are LDS.64; the
// (gp, gp+4) bank-colliding lane pairs land in different phases -> conflict-free.
// B in smem stride 72, natural k-pair order -> LDS.64. Single-pass fp16 mma.
template <int OUTC>
__global__ void __launch_bounds__(256, (OUTC == 64) ? 4 : 2)
k_gemm(const __half* __restrict__ Xh, __half* __restrict__ Z) {
    extern __shared__ uint32_t sm[];
    uint32_t* As = sm;                  // 128*72 words
    uint32_t* Bs = sm + 128 * 72;       // OUTC*72 words
    int tid = threadIdx.x;
    int base = blockIdx.x * 128;

    // stage A via cp.async: 128 rows x 16 chunks of 16B, row stride 72 words
    {
        uint32_t abase = s2u(As);
#pragma unroll
        for (int it = 0; it < 8; it++) {
            int i = tid + it * 256;          // 0..2047
            int row = i >> 4, c = i & 15;
            int v = base + row;
            if (v >= NN) v = NN - 1;         // clamp (finite garbage, never stored)
            cp16(abase + (uint32_t)(row * 72 + c * 4) * 4, Xh + (size_t)v * DH + c * 8);
        }
        asm volatile("cp.async.commit_group;");
    }
    // stage B from packed global (uint4 copies, pad 64 -> 72 stride)
    {
        const uint4* gw = (const uint4*)g_wb;
        for (int i = tid; i < OUTC * 16; i += 256) {
            int col = i >> 4, q = i & 15;
            *(uint4*)&Bs[col * 72 + q * 4] = gw[i];
        }
    }
    asm volatile("cp.async.wait_group 0;" ::: "memory");
    __syncthreads();

    int wid = tid >> 5, lane = tid & 31;
    int gp = lane >> 2, qp = lane & 3;
    int r0 = wid * 16 + gp;
    int v0 = base + r0, v8 = v0 + 8;
    bool q0 = v0 < NN, q8 = v8 < NN;

    constexpr int NJ = OUTC / 8;        // n-tiles per warp (full N)
    float acc[NJ][4];
#pragma unroll
    for (int j = 0; j < NJ; j++) {
        acc[j][0] = 0.f; acc[j][1] = 0.f; acc[j][2] = 0.f; acc[j][3] = 0.f;
    }

#pragma unroll
    for (int ks = 0; ks < 8; ks++) {
        int fo = ks * 8 + qp * 2;
        uint2 a0 = *(const uint2*)&As[r0 * 72 + fo];
        uint2 a1 = *(const uint2*)&As[(r0 + 8) * 72 + fo];
        uint32_t a[4] = {a0.x, a1.x, a0.y, a1.y};
#pragma unroll
        for (int j = 0; j < NJ; j++) {
            int c = (j * 8 + gp) * 72 + fo;
            uint2 b = *(const uint2*)&Bs[c];
            mma_f16(acc[j], a, b.x, b.y);
        }
    }

    // epilogue: dinv from degree, scale, store fp16
    float d0 = q0 ? rsqrtf((float)g_deg[v0] + 1.f) : 0.f;
    float d8 = q8 ? rsqrtf((float)g_deg[v8] + 1.f) : 0.f;
#pragma unroll
    for (int j = 0; j < NJ; j++) {
        int col = j * 8 + qp * 2;
        if (q0)
            *(__half2*)(Z + (size_t)v0 * OUTC + col) =
                __float22half2_rn(make_float2(d0 * acc[j][0], d0 * acc[j][1]));
        if (q8)
            *(__half2*)(Z + (size_t)v8 * OUTC + col) =
                __float22half2_rn(make_float2(d8 * acc[j][2], d8 * acc[j][3]));
    }
}

// ---------------- aggregation: 1 row/load, 8-deep MLP; optional fp16 output ----------------
template <int VPT>
__device__ __forceinline__ void ld_row(uint32_t* r, const __half* __restrict__ Z,
                                       int s, int lane) {
    const char* p = (const char*)(Z) + ((size_t)s * (VPT * 32) + lane * VPT) * 2;
    if (VPT == 4) {
        uint2 x = *(const uint2*)p;
        r[0] = x.x; r[1] = x.y;
    } else {
        r[0] = *(const uint32_t*)p;
    }
}
template <int VPT>
__device__ __forceinline__ void acc_row(float* acc, const uint32_t* r) {
#pragma unroll
    for (int q = 0; q < VPT / 2; q++) {
        float2 f = __half22float2(*(const __half2*)&r[q]);
        acc[2 * q] += f.x;
        acc[2 * q + 1] += f.y;
    }
}

template <int OUTC, bool RELU, bool LSM, bool HOUT>
__global__ void k_agg(const __half* __restrict__ Z, const float* __restrict__ bias,
                      void* __restrict__ outv) {
    int v = (blockIdx.x * blockDim.x + threadIdx.x) >> 5;
    if (v >= NN) return;
    int lane = threadIdx.x & 31;
    constexpr int VPT = OUTC / 32;
    float acc[VPT];
#pragma unroll
    for (int i = 0; i < VPT; i++) acc[i] = 0.f;

    // self term
    {
        uint32_t r[VPT / 2];
        ld_row<VPT>(r, Z, v, lane);
        acc_row<VPT>(acc, r);
    }

    int start = g_rowptr[v];
    int cnt = g_deg[v];
    if (LSM) {
        // final layer: reset degree for the next kernel_launch call (deterministic
        // state cycle: module-load zero-init covers the first call)
        if (lane == 0) g_deg[v] = 0;
    }
    int e = 0;
    for (; e + 8 <= cnt; e += 8) {   // 8 independent gathers in flight
        int s0 = g_csr[start + e + 0];
        int s1 = g_csr[start + e + 1];
        int s2 = g_csr[start + e + 2];
        int s3 = g_csr[start + e + 3];
        int s4 = g_csr[start + e + 4];
        int s5 = g_csr[start + e + 5];
        int s6 = g_csr[start + e + 6];
        int s7 = g_csr[start + e + 7];
        uint32_t r0[VPT / 2], r1[VPT / 2], r2[VPT / 2], r3[VPT / 2];
        uint32_t r4[VPT / 2], r5[VPT / 2], r6[VPT / 2], r7[VPT / 2];
        ld_row<VPT>(r0, Z, s0, lane);
        ld_row<VPT>(r1, Z, s1, lane);
        ld_row<VPT>(r2, Z, s2, lane);
        ld_row<VPT>(r3, Z, s3, lane);
        ld_row<VPT>(r4, Z, s4, lane);
        ld_row<VPT>(r5, Z, s5, lane);
        ld_row<VPT>(r6, Z, s6, lane);
        ld_row<VPT>(r7, Z, s7, lane);
        acc_row<VPT>(acc, r0);
        acc_row<VPT>(acc, r1);
        acc_row<VPT>(acc, r2);
        acc_row<VPT>(acc, r3);
        acc_row<VPT>(acc, r4);
        acc_row<VPT>(acc, r5);
        acc_row<VPT>(acc, r6);
        acc_row<VPT>(acc, r7);
    }
    if (e + 4 <= cnt) {
        int s0 = g_csr[start + e + 0];
        int s1 = g_csr[start + e + 1];
        int s2 = g_csr[start + e + 2];
        int s3 = g_csr[start + e + 3];
        uint32_t r0[VPT / 2], r1[VPT / 2], r2[VPT / 2], r3[VPT / 2];
        ld_row<VPT>(r0, Z, s0, lane);
        ld_row<VPT>(r1, Z, s1, lane);
        ld_row<VPT>(r2, Z, s2, lane);
        ld_row<VPT>(r3, Z, s3, lane);
        acc_row<VPT>(acc, r0);
        acc_row<VPT>(acc, r1);
        acc_row<VPT>(acc, r2);
        acc_row<VPT>(acc, r3);
        e += 4;
    }
    for (; e < cnt; e++) {
        uint32_t r[VPT / 2];
        ld_row<VPT>(r, Z, g_csr[start + e], lane);
        acc_row<VPT>(acc, r);
    }

    float dv = rsqrtf((float)cnt + 1.f);
    float h[VPT];
#pragma unroll
    for (int i = 0; i < VPT; i++) {
        h[i] = fmaf(dv, acc[i], bias[lane * VPT + i]);
        if (RELU) h[i] = fmaxf(h[i], 0.f);
    }
    if (LSM) {
        float m = h[0];
#pragma unroll
        for (int i = 1; i < VPT; i++) m = fmaxf(m, h[i]);
#pragma unroll
        for (int off = 16; off > 0; off >>= 1)
            m = fmaxf(m, __shfl_xor_sync(0xffffffffu, m, off));
        float s = 0.f;
#pragma unroll
        for (int i = 0; i < VPT; i++) s += expf(h[i] - m);
#pragma unroll
        for (int off = 16; off > 0; off >>= 1)
            s += __shfl_xor_sync(0xffffffffu, s, off);
        float l = m + logf(s);
#pragma unroll
        for (int i = 0; i < VPT; i++) h[i] -= l;
    }

    if (HOUT) {
        __half* op = (__half*)outv + (size_t)v * OUTC + lane * VPT;
        if (VPT == 4) {
            uint2 o;
            o.x = packh2(h[0], h[1]);
            o.y = packh2(h[2], h[3]);
            *(uint2*)op = o;
        } else {
            *(uint32_t*)op = packh2(h[0], h[1]);
        }
    } else {
        float* op = (float*)outv + (size_t)v * OUTC + lane * VPT;
        if (VPT == 4) {
            *(float4*)op = make_float4(h[0], h[1], h[2], h[3]);
        } else {
            *(float2*)op = make_float2(h[0], h[1]);
        }
    }
}

// ---------------- launch ----------------
extern "C" void kernel_launch(void* const* d_in, const int* in_sizes, int n_in,
                              void* d_out, int out_size) {
    const int*   edges = (const int*)d_in[0];
    const int*   esrc  = edges;
    const int*   edst  = edges + NE;
    const float* X  = (const float*)d_in[1];
    const float* W0 = (const float*)d_in[2];
    const float* b0 = (const float*)d_in[3];
    const float* W1 = (const float*)d_in[4];
    const float* b1 = (const float*)d_in[5];
    const float* W2 = (const float*)d_in[6];
    const float* b2 = (const float*)d_in[7];
    float* out = (float*)d_out;

    __half* zp;
    __half* hp;   // doubles as fp16-X storage before agg1 overwrites it
    cudaGetSymbolAddress((void**)&zp, g_z4);
    cudaGetSymbolAddress((void**)&hp, g_hh);

    const int SMEM_A    = 128 * 72 * 4;             // 36864
    const int SMEM_G128 = SMEM_A + DH * 72 * 4;     // 73728
    const int SMEM_G64  = SMEM_A + DO * 72 * 4;     // 55296
    cudaFuncSetAttribute(k_gemm<DH>, cudaFuncAttributeMaxDynamicSharedMemorySize, SMEM_G128);
    cudaFuncSetAttribute(k_gemm<DO>, cudaFuncAttributeMaxDynamicSharedMemorySize, SMEM_G64);

    const int scan_blocks = (NN + 1023) / 1024;   // 98
    const int gemm_blocks = (NN + 127) / 128;     // 782
    const int agg_blocks  = NN / 8;               // 12500

    // launch order puts gemm L1 at slot 4 (profiled by ncu -s 5 -c 1)
    k_wconv<<<(DH * 64 + 255) / 256, 256>>>(W0, DH);              // 1
    k_xconv<<<(NN * DH / 4 + 255) / 256, 256>>>(X, hp);           // 2
    k_hist<<<(NE + 255) / 256, 256>>>(edst);                      // 3 (deg ready; zeroed by prev call's final agg)
    k_gemm<DH><<<gemm_blocks, 256, SMEM_G128>>>(hp, zp);          // 4 <- profiled
    k_scan1<<<scan_blocks, 1024>>>();                             // 5
    k_scan3<<<scan_blocks, 1024>>>(scan_blocks);                  // 6 (bsum scan fused, fill zeroed)
    k_csr<<<(NE + 255) / 256, 256>>>(esrc, edst);                 // 7

    // layer 1 agg (fp16 H out; overwrites the X16 staging)
    k_agg<DH, true, false, true><<<agg_blocks, 256>>>(zp, b0, hp);

    // layer 2
    k_wconv<<<(DH * 64 + 255) / 256, 256>>>(W1, DH);
    k_gemm<DH><<<gemm_blocks, 256, SMEM_G128>>>(hp, zp);
    k_agg<DH, true, false, true><<<agg_blocks, 256>>>(zp, b1, hp);

    // layer 3 + log_softmax (fp32 out; also resets g_deg for next call)
    k_wconv<<<(DO * 64 + 255) / 256, 256>>>(W2, DO);
    k_gemm<DO><<<gemm_blocks, 256, SMEM_G64>>>(hp, zp);
    k_agg<DO, false, true, false><<<agg_blocks, 256>>>(zp, b2, out);
}

// round 17
// speedup vs baseline: 1.0061x; 1.0061x over previous
#include <cuda_runtime.h>
#include <cuda_fp16.h>
#include <math.h>
#include <stdint.h>

#define NN 100000
#define NE 1600000
#define DH 128
#define DO 64

// ---------------- device scratch (static; no allocation allowed) ----------------
__device__ int      g_deg[NN];      // zero-initialized at load; re-zeroed by final agg each call
__device__ int      g_fill[NN];     // zeroed by k_scan3 each call (before k_csr)
__device__ int      g_rowptr[NN];
__device__ int      g_csr[NE];
__device__ uint4    g_z4[(size_t)NN * DH * 2 / 16];   // fp16 Z backing
__device__ uint4    g_hh[(size_t)NN * DH * 2 / 16];   // fp16 H backing (also holds X16 before agg1)
__device__ int      g_bsums[128];
__device__ uint32_t g_wb[128 * 64];   // packed fp16x2 weights, natural k-pair order

// ---------------- helpers ----------------
__device__ __forceinline__ uint32_t packh2(float x, float y) {
    __half2 h = __floats2half2_rn(x, y);
    return *(uint32_t*)&h;
}
__device__ __forceinline__ uint32_t s2u(const void* p) {
    uint32_t a;
    asm("{ .reg .u64 t; cvta.to.shared.u64 t, %1; cvt.u32.u64 %0, t; }" : "=r"(a) : "l"(p));
    return a;
}
__device__ __forceinline__ void cp16(uint32_t dst, const void* src) {
    asm volatile("cp.async.cg.shared.global [%0], [%1], 16;" :: "r"(dst), "l"(src));
}

__device__ __forceinline__ void mma_f16(float* c, const uint32_t* a, uint32_t b0, uint32_t b1) {
    asm volatile(
        "mma.sync.aligned.m16n8k16.row.col.f32.f16.f16.f32 "
        "{%0,%1,%2,%3}, {%4,%5,%6,%7}, {%8,%9}, {%0,%1,%2,%3};"
        : "+f"(c[0]), "+f"(c[1]), "+f"(c[2]), "+f"(c[3])
        : "r"(a[0]), "r"(a[1]), "r"(a[2]), "r"(a[3]), "r"(b0), "r"(b1));
}

// ---------------- prep kernels ----------------
__global__ void k_hist(const int* __restrict__ dst) {
    int i = blockIdx.x * 256 + threadIdx.x;
    if (i < NE) atomicAdd(&g_deg[dst[i]], 1);
}
__global__ void k_scan1() {
    __shared__ int s[1024];
    int t = threadIdx.x;
    int i = blockIdx.x * 1024 + t;
    int val = (i < NN) ? g_deg[i] : 0;
    s[t] = val;
    __syncthreads();
    for (int off = 1; off < 1024; off <<= 1) {
        int x = (t >= off) ? s[t - off] : 0;
        __syncthreads();
        if (t >= off) s[t] += x;
        __syncthreads();
    }
    if (i < NN) g_rowptr[i] = s[t] - val;
    if (t == 1023) g_bsums[blockIdx.x] = s[1023];
}
// scan of block sums fused in (every block redundantly scans the 98 bsums),
// plus g_fill zeroing for k_csr.
__global__ void k_scan3(int nb) {
    __shared__ int s[128];
    __shared__ int excl;
    int t = threadIdx.x;
    int val = 0;
    if (t < 128) { val = (t < nb) ? g_bsums[t] : 0; s[t] = val; }
    __syncthreads();
    for (int off = 1; off < 128; off <<= 1) {
        int x = (t < 128 && t >= off) ? s[t - off] : 0;
        __syncthreads();
        if (t < 128 && t >= off) s[t] += x;
        __syncthreads();
    }
    if (t == (int)blockIdx.x) excl = s[t] - val;   // exclusive prefix of this block
    __syncthreads();
    int i = blockIdx.x * 1024 + t;
    if (i < NN) { g_rowptr[i] += excl; g_fill[i] = 0; }
}
__global__ void k_csr(const int* __restrict__ src, const int* __restrict__ dst) {
    int i = blockIdx.x * 256 + threadIdx.x;
    if (i < NE) {
        int d = dst[i];
        int pos = g_rowptr[d] + atomicAdd(&g_fill[d], 1);
        g_csr[pos] = src[i];
    }
}

// ---------------- conversions ----------------
// weights: fp32 -> fp16x2, natural k-pair order (k-perm: thread qp owns phys k 16ks+4qp..+3)
__global__ void k_wconv(const float* __restrict__ W, int outc) {
    int i = blockIdx.x * 256 + threadIdx.x;
    if (i >= outc * 64) return;
    int col = i >> 6, kp = i & 63;
    g_wb[col * 64 + kp] = packh2(W[(2 * kp) * outc + col], W[(2 * kp + 1) * outc + col]);
}
// X: fp32 -> fp16, streaming
__global__ void k_xconv(const float* __restrict__ X, __half* __restrict__ Xh) {
    int i = blockIdx.x * 256 + threadIdx.x;   // handles 4 floats
    if (i < NN * DH / 4) {
        float4 x = ((const float4*)X)[i];
        uint2 o;
        o.x = packh2(x.x, x.y);
        o.y = packh2(x.z, x.w);
        ((uint2*)Xh)[i] = o;
    }
}

// ---------------- mma.sync GEMM: Z[v][t] = dinv[v] * dot(X[v,:], W[:,t]) ----------------
// M-tile 128, block 256 (8 warps): warp wid owns rows wid*16..+15, FULL N.
// A (fp16) staged verbatim via cp.async into smem rows of stride 72 words (288B):
// coalesced 16B granules, no ALU, no scatter. Fragment loads are LDS.64.
// B in smem stride 72, natural k-pair order -> LDS.64. Single-pass fp16 mma.
// NOTE: min-blocks MUST stay 2 — forcing 4 caps regs at 64 and spills (R16 lesson).
template <int OUTC>
__global__ void __launch_bounds__(256, 2)
k_gemm(const __half* __restrict__ Xh, __half* __restrict__ Z) {
    extern __shared__ uint32_t sm[];
    uint32_t* As = sm;                  // 128*72 words
    uint32_t* Bs = sm + 128 * 72;       // OUTC*72 words
    int tid = threadIdx.x;
    int base = blockIdx.x * 128;

    // stage A via cp.async: 128 rows x 16 chunks of 16B, row stride 72 words
    {
        uint32_t abase = s2u(As);
#pragma unroll
        for (int it = 0; it < 8; it++) {
            int i = tid + it * 256;          // 0..2047
            int row = i >> 4, c = i & 15;
            int v = base + row;
            if (v >= NN) v = NN - 1;         // clamp (finite garbage, never stored)
            cp16(abase + (uint32_t)(row * 72 + c * 4) * 4, Xh + (size_t)v * DH + c * 8);
        }
        asm volatile("cp.async.commit_group;");
    }
    // stage B from packed global (uint4 copies, pad 64 -> 72 stride)
    {
        const uint4* gw = (const uint4*)g_wb;
        for (int i = tid; i < OUTC * 16; i += 256) {
            int col = i >> 4, q = i & 15;
            *(uint4*)&Bs[col * 72 + q * 4] = gw[i];
        }
    }
    asm volatile("cp.async.wait_group 0;" ::: "memory");
    __syncthreads();

    int wid = tid >> 5, lane = tid & 31;
    int gp = lane >> 2, qp = lane & 3;
    int r0 = wid * 16 + gp;
    int v0 = base + r0, v8 = v0 + 8;
    bool q0 = v0 < NN, q8 = v8 < NN;

    constexpr int NJ = OUTC / 8;        // n-tiles per warp (full N)
    float acc[NJ][4];
#pragma unroll
    for (int j = 0; j < NJ; j++) {
        acc[j][0] = 0.f; acc[j][1] = 0.f; acc[j][2] = 0.f; acc[j][3] = 0.f;
    }

#pragma unroll
    for (int ks = 0; ks < 8; ks++) {
        int fo = ks * 8 + qp * 2;
        uint2 a0 = *(const uint2*)&As[r0 * 72 + fo];
        uint2 a1 = *(const uint2*)&As[(r0 + 8) * 72 + fo];
        uint32_t a[4] = {a0.x, a1.x, a0.y, a1.y};
#pragma unroll
        for (int j = 0; j < NJ; j++) {
            int c = (j * 8 + gp) * 72 + fo;
            uint2 b = *(const uint2*)&Bs[c];
            mma_f16(acc[j], a, b.x, b.y);
        }
    }

    // epilogue: dinv from degree, scale, store fp16
    float d0 = q0 ? rsqrtf((float)g_deg[v0] + 1.f) : 0.f;
    float d8 = q8 ? rsqrtf((float)g_deg[v8] + 1.f) : 0.f;
#pragma unroll
    for (int j = 0; j < NJ; j++) {
        int col = j * 8 + qp * 2;
        if (q0)
            *(__half2*)(Z + (size_t)v0 * OUTC + col) =
                __float22half2_rn(make_float2(d0 * acc[j][0], d0 * acc[j][1]));
        if (q8)
            *(__half2*)(Z + (size_t)v8 * OUTC + col) =
                __float22half2_rn(make_float2(d8 * acc[j][2], d8 * acc[j][3]));
    }
}

// ---------------- aggregation: 1 row/load, 8-deep MLP; optional fp16 output ----------------
template <int VPT>
__device__ __forceinline__ void ld_row(uint32_t* r, const __half* __restrict__ Z,
                                       int s, int lane) {
    const char* p = (const char*)(Z) + ((size_t)s * (VPT * 32) + lane * VPT) * 2;
    if (VPT == 4) {
        uint2 x = *(const uint2*)p;
        r[0] = x.x; r[1] = x.y;
    } else {
        r[0] = *(const uint32_t*)p;
    }
}
template <int VPT>
__device__ __forceinline__ void acc_row(float* acc, const uint32_t* r) {
#pragma unroll
    for (int q = 0; q < VPT / 2; q++) {
        float2 f = __half22float2(*(const __half2*)&r[q]);
        acc[2 * q] += f.x;
        acc[2 * q + 1] += f.y;
    }
}

template <int OUTC, bool RELU, bool LSM, bool HOUT>
__global__ void k_agg(const __half* __restrict__ Z, const float* __restrict__ bias,
                      void* __restrict__ outv) {
    int v = (blockIdx.x * blockDim.x + threadIdx.x) >> 5;
    if (v >= NN) return;
    int lane = threadIdx.x & 31;
    constexpr int VPT = OUTC / 32;
    float acc[VPT];
#pragma unroll
    for (int i = 0; i < VPT; i++) acc[i] = 0.f;

    // self term
    {
        uint32_t r[VPT / 2];
        ld_row<VPT>(r, Z, v, lane);
        acc_row<VPT>(acc, r);
    }

    int start = g_rowptr[v];
    int cnt = g_deg[v];
    if (LSM) {
        // final layer: reset degree for the next kernel_launch call (deterministic
        // state cycle: module-load zero-init covers the first call)
        if (lane == 0) g_deg[v] = 0;
    }
    int e = 0;
    for (; e + 8 <= cnt; e += 8) {   // 8 independent gathers in flight
        int s0 = g_csr[start + e + 0];
        int s1 = g_csr[start + e + 1];
        int s2 = g_csr[start + e + 2];
        int s3 = g_csr[start + e + 3];
        int s4 = g_csr[start + e + 4];
        int s5 = g_csr[start + e + 5];
        int s6 = g_csr[start + e + 6];
        int s7 = g_csr[start + e + 7];
        uint32_t r0[VPT / 2], r1[VPT / 2], r2[VPT / 2], r3[VPT / 2];
        uint32_t r4[VPT / 2], r5[VPT / 2], r6[VPT / 2], r7[VPT / 2];
        ld_row<VPT>(r0, Z, s0, lane);
        ld_row<VPT>(r1, Z, s1, lane);
        ld_row<VPT>(r2, Z, s2, lane);
        ld_row<VPT>(r3, Z, s3, lane);
        ld_row<VPT>(r4, Z, s4, lane);
        ld_row<VPT>(r5, Z, s5, lane);
        ld_row<VPT>(r6, Z, s6, lane);
        ld_row<VPT>(r7, Z, s7, lane);
        acc_row<VPT>(acc, r0);
        acc_row<VPT>(acc, r1);
        acc_row<VPT>(acc, r2);
        acc_row<VPT>(acc, r3);
        acc_row<VPT>(acc, r4);
        acc_row<VPT>(acc, r5);
        acc_row<VPT>(acc, r6);
        acc_row<VPT>(acc, r7);
    }
    if (e + 4 <= cnt) {
        int s0 = g_csr[start + e + 0];
        int s1 = g_csr[start + e + 1];
        int s2 = g_csr[start + e + 2];
        int s3 = g_csr[start + e + 3];
        uint32_t r0[VPT / 2], r1[VPT / 2], r2[VPT / 2], r3[VPT / 2];
        ld_row<VPT>(r0, Z, s0, lane);
        ld_row<VPT>(r1, Z, s1, lane);
        ld_row<VPT>(r2, Z, s2, lane);
        ld_row<VPT>(r3, Z, s3, lane);
        acc_row<VPT>(acc, r0);
        acc_row<VPT>(acc, r1);
        acc_row<VPT>(acc, r2);
        acc_row<VPT>(acc, r3);
        e += 4;
    }
    for (; e < cnt; e++) {
        uint32_t r[VPT / 2];
        ld_row<VPT>(r, Z, g_csr[start + e], lane);
        acc_row<VPT>(acc, r);
    }

    float dv = rsqrtf((float)cnt + 1.f);
    float h[VPT];
#pragma unroll
    for (int i = 0; i < VPT; i++) {
        h[i] = fmaf(dv, acc[i], bias[lane * VPT + i]);
        if (RELU) h[i] = fmaxf(h[i], 0.f);
    }
    if (LSM) {
        float m = h[0];
#pragma unroll
        for (int i = 1; i < VPT; i++) m = fmaxf(m, h[i]);
#pragma unroll
        for (int off = 16; off > 0; off >>= 1)
            m = fmaxf(m, __shfl_xor_sync(0xffffffffu, m, off));
        float s = 0.f;
#pragma unroll
        for (int i = 0; i < VPT; i++) s += expf(h[i] - m);
#pragma unroll
        for (int off = 16; off > 0; off >>= 1)
            s += __shfl_xor_sync(0xffffffffu, s, off);
        float l = m + logf(s);
#pragma unroll
        for (int i = 0; i < VPT; i++) h[i] -= l;
    }

    if (HOUT) {
        __half* op = (__half*)outv + (size_t)v * OUTC + lane * VPT;
        if (VPT == 4) {
            uint2 o;
            o.x = packh2(h[0], h[1]);
            o.y = packh2(h[2], h[3]);
            *(uint2*)op = o;
        } else {
            *(uint32_t*)op = packh2(h[0], h[1]);
        }
    } else {
        float* op = (float*)outv + (size_t)v * OUTC + lane * VPT;
        if (VPT == 4) {
            *(float4*)op = make_float4(h[0], h[1], h[2], h[3]);
        } else {
            *(float2*)op = make_float2(h[0], h[1]);
        }
    }
}

// ---------------- launch ----------------
extern "C" void kernel_launch(void* const* d_in, const int* in_sizes, int n_in,
                              void* d_out, int out_size) {
    const int*   edges = (const int*)d_in[0];
    const int*   esrc  = edges;
    const int*   edst  = edges + NE;
    const float* X  = (const float*)d_in[1];
    const float* W0 = (const float*)d_in[2];
    const float* b0 = (const float*)d_in[3];
    const float* W1 = (const float*)d_in[4];
    const float* b1 = (const float*)d_in[5];
    const float* W2 = (const float*)d_in[6];
    const float* b2 = (const float*)d_in[7];
    float* out = (float*)d_out;

    __half* zp;
    __half* hp;   // doubles as fp16-X storage before agg1 overwrites it
    cudaGetSymbolAddress((void**)&zp, g_z4);
    cudaGetSymbolAddress((void**)&hp, g_hh);

    const int SMEM_A    = 128 * 72 * 4;             // 36864
    const int SMEM_G128 = SMEM_A + DH * 72 * 4;     // 73728
    const int SMEM_G64  = SMEM_A + DO * 72 * 4;     // 55296
    cudaFuncSetAttribute(k_gemm<DH>, cudaFuncAttributeMaxDynamicSharedMemorySize, SMEM_G128);
    cudaFuncSetAttribute(k_gemm<DO>, cudaFuncAttributeMaxDynamicSharedMemorySize, SMEM_G64);

    const int scan_blocks = (NN + 1023) / 1024;   // 98
    const int gemm_blocks = (NN + 127) / 128;     // 782
    const int agg_blocks  = NN / 8;               // 12500

    // launch order puts gemm L1 at slot 4 (profiled by ncu -s 5 -c 1)
    k_wconv<<<(DH * 64 + 255) / 256, 256>>>(W0, DH);              // 1
    k_xconv<<<(NN * DH / 4 + 255) / 256, 256>>>(X, hp);           // 2
    k_hist<<<(NE + 255) / 256, 256>>>(edst);                      // 3 (deg ready; zeroed by prev call's final agg)
    k_gemm<DH><<<gemm_blocks, 256, SMEM_G128>>>(hp, zp);          // 4 <- profiled
    k_scan1<<<scan_blocks, 1024>>>();                             // 5
    k_scan3<<<scan_blocks, 1024>>>(scan_blocks);                  // 6 (bsum scan fused, fill zeroed)
    k_csr<<<(NE + 255) / 256, 256>>>(esrc, edst);                 // 7

    // layer 1 agg (fp16 H out; overwrites the X16 staging)
    k_agg<DH, true, false, true><<<agg_blocks, 256>>>(zp, b0, hp);

    // layer 2
    k_wconv<<<(DH * 64 + 255) / 256, 256>>>(W1, DH);
    k_gemm<DH><<<gemm_blocks, 256, SMEM_G128>>>(hp, zp);
    k_agg<DH, true, false, true><<<agg_blocks, 256>>>(zp, b1, hp);

    // layer 3 + log_softmax (fp32 out; also resets g_deg for next call)
    k_wconv<<<(DO * 64 + 255) / 256, 256>>>(W2, DO);
    k_gemm<DO><<<gemm_blocks, 256, SMEM_G64>>>(hp, zp);
    k_agg<DO, false, true, false><<<agg_blocks, 256>>>(zp, b2, out);
}